// round 7
// baseline (speedup 1.0000x reference)
#include <cuda_runtime.h>
#include <cuda_bf16.h>
#include <cstdint>

#define BATCH 4
#define SEQ   2048
#define NH    16
#define HD    64
#define HID   1024
#define QKV3  3072
#define MROWS (BATCH * SEQ)        // 8192

// 0.125 * log2(e): folded into Q at the QKV epilogue (softmax in base-2 domain)
#define QSF 0.18033688011112042f

// ---------------------------------------------------------------------------
// Scratch (static device globals — allocation-free per harness rules)
// ---------------------------------------------------------------------------
__device__ __nv_bfloat16 g_qh[MROWS * QKV3];           // qkv hi split (48 MB)
__device__ __nv_bfloat16 g_ql[MROWS * QKV3];           // qkv lo split
__device__ int           g_mask[BATCH * SEQ];
__device__ unsigned long long g_mbits[BATCH * 32];     // 64-key tile bitmasks
__device__ __nv_bfloat16 g_sh[MROWS * HID];            // activation hi (hidden, then attn out)
__device__ __nv_bfloat16 g_sl[MROWS * HID];            // activation lo
__device__ __nv_bfloat16 g_wh[(QKV3 + HID) * HID];     // W^T hi
__device__ __nv_bfloat16 g_wl[(QKV3 + HID) * HID];     // W^T lo

// ---------------------------------------------------------------------------
// PTX helpers (arch-portable sm_80+; tcgen05 unavailable via compute_103)
// ---------------------------------------------------------------------------
__device__ __forceinline__ uint32_t smem_u32(const void* p) {
    uint32_t a;
    asm("{ .reg .u64 t; cvta.to.shared.u64 t, %1; cvt.u32.u64 %0, t; }" : "=r"(a) : "l"(p));
    return a;
}
__device__ __forceinline__ void ldsm_x4(uint32_t& r0, uint32_t& r1, uint32_t& r2, uint32_t& r3,
                                        uint32_t addr) {
    asm volatile("ldmatrix.sync.aligned.m8n8.x4.shared.b16 {%0,%1,%2,%3}, [%4];"
                 : "=r"(r0), "=r"(r1), "=r"(r2), "=r"(r3) : "r"(addr));
}
__device__ __forceinline__ void ldsm_x4t(uint32_t& r0, uint32_t& r1, uint32_t& r2, uint32_t& r3,
                                         uint32_t addr) {
    asm volatile("ldmatrix.sync.aligned.m8n8.x4.trans.shared.b16 {%0,%1,%2,%3}, [%4];"
                 : "=r"(r0), "=r"(r1), "=r"(r2), "=r"(r3) : "r"(addr));
}
__device__ __forceinline__ void mma_bf16(float* c, const uint32_t* a, uint32_t b0, uint32_t b1) {
    asm volatile(
        "mma.sync.aligned.m16n8k16.row.col.f32.bf16.bf16.f32 "
        "{%0,%1,%2,%3}, {%4,%5,%6,%7}, {%8,%9}, {%0,%1,%2,%3};"
        : "+f"(c[0]), "+f"(c[1]), "+f"(c[2]), "+f"(c[3])
        : "r"(a[0]), "r"(a[1]), "r"(a[2]), "r"(a[3]), "r"(b0), "r"(b1));
}
__device__ __forceinline__ float fexp2(float x) {
    float y; asm("ex2.approx.f32 %0, %1;" : "=f"(y) : "f"(x)); return y;
}
__device__ __forceinline__ void split_pack(float x, float y, uint32_t& hp, uint32_t& lp) {
    __nv_bfloat162 hv, lv;
    hv.x = __float2bfloat16(x);
    hv.y = __float2bfloat16(y);
    lv.x = __float2bfloat16(x - __bfloat162float(hv.x));
    lv.y = __float2bfloat16(y - __bfloat162float(hv.y));
    hp = *(uint32_t*)&hv;
    lp = *(uint32_t*)&lv;
}
#define CP_ASYNC16(dst, src) \
    asm volatile("cp.async.cg.shared.global [%0], [%1], 16;" :: "r"(dst), "l"(src))
#define CP_COMMIT() asm volatile("cp.async.commit_group;" ::: "memory")
#define CP_WAIT(n)  asm volatile("cp.async.wait_group %0;" :: "n"(n) : "memory")

// ---------------------------------------------------------------------------
// Mask canonicalizer + per-64-key-tile bitmasks
// ---------------------------------------------------------------------------
__global__ void mask_convert_kernel(const void* __restrict__ raw, int n) {
    __shared__ int mode;
    if (threadIdx.x == 0) {
        unsigned w0 = ((const unsigned*)raw)[0];
        if (w0 == 1u || w0 == 0u)    mode = 0;  // int32
        else if (w0 == 0x3F800000u)  mode = 1;  // float32
        else if (w0 == 0x01010101u)  mode = 2;  // uint8
        else if (w0 == 0x3F803F80u)  mode = 3;  // bf16 pair
        else                          mode = 2;
    }
    __syncthreads();
    int m = mode;
    for (int i = threadIdx.x; i < n; i += blockDim.x) {
        int v;
        if (m == 0)      v = (((const int*)raw)[i] != 0);
        else if (m == 1) v = (((const float*)raw)[i] != 0.0f);
        else if (m == 2) v = (((const unsigned char*)raw)[i] != 0);
        else { unsigned short h = ((const unsigned short*)raw)[i]; v = ((h & 0x7FFF) != 0); }
        g_mask[i] = v;
    }
    __syncthreads();
    for (int t = threadIdx.x; t < BATCH * 32; t += blockDim.x) {
        int b = t >> 5, kt = t & 31;
        unsigned long long mb = 0ull;
        for (int j = 0; j < 64; j++)
            mb |= ((unsigned long long)(g_mask[b * SEQ + kt * 64 + j] & 1)) << j;
        g_mbits[t] = mb;
    }
}

// ---------------------------------------------------------------------------
// bf16 split kernels (hidden input + weights)
// ---------------------------------------------------------------------------
__global__ void splitA_kernel(const float* __restrict__ A,
                              __nv_bfloat16* __restrict__ Ah,
                              __nv_bfloat16* __restrict__ Al, int n4) {
    int stride = gridDim.x * blockDim.x;
    for (int i = blockIdx.x * blockDim.x + threadIdx.x; i < n4; i += stride) {
        float4 v = ((const float4*)A)[i];
        uint32_t h0, l0, h1, l1;
        split_pack(v.x, v.y, h0, l0);
        split_pack(v.z, v.w, h1, l1);
        ((uint32_t*)Ah)[i * 2]     = h0;
        ((uint32_t*)Ah)[i * 2 + 1] = h1;
        ((uint32_t*)Al)[i * 2]     = l0;
        ((uint32_t*)Al)[i * 2 + 1] = l1;
    }
}

// B [K,N] fp32 -> B^T [N,K] bf16 hi/lo
__global__ void splitBT_kernel(const float* __restrict__ B,
                               __nv_bfloat16* __restrict__ BTh,
                               __nv_bfloat16* __restrict__ BTl, int K, int N) {
    __shared__ float tile[32][33];
    int k0 = blockIdx.y * 32, n0 = blockIdx.x * 32;
    int tx = threadIdx.x & 31, ty = threadIdx.x >> 5;
    for (int r = ty; r < 32; r += 8)
        tile[r][tx] = B[(size_t)(k0 + r) * N + n0 + tx];
    __syncthreads();
    for (int r = ty; r < 32; r += 8) {
        float v = tile[tx][r];
        __nv_bfloat16 h = __float2bfloat16(v);
        __nv_bfloat16 l = __float2bfloat16(v - __bfloat162float(h));
        size_t o = (size_t)(n0 + r) * K + k0 + tx;
        BTh[o] = h;
        BTl[o] = l;
    }
}

// ---------------------------------------------------------------------------
// mma.sync bf16x3 GEMM. 4 warps, 64x64 warp tile (6 MMA per LDSM.x4),
// CTA 128x128, 2-stage cp.async, 2 CTAs/SM.
// MODE 0: bf16 hi/lo output + Q-scale on cols < HID. MODE 1: fp32 + bias.
// ---------------------------------------------------------------------------
#define KC        32
#define TROW      80
#define TILE_B    (128 * TROW)
#define STAGE_B   (4 * TILE_B)          // 40960: Ah | Al | Bh | Bl
#define TC_SMEM   (2 * STAGE_B)         // 81920 -> 2 CTAs/SM

template <int MODE>
__global__ __launch_bounds__(128, 2)
void mma_gemm_kernel(const __nv_bfloat16* __restrict__ Ah, const __nv_bfloat16* __restrict__ Al,
                     const __nv_bfloat16* __restrict__ BTh, const __nv_bfloat16* __restrict__ BTl,
                     const float* __restrict__ bias, float* __restrict__ C,
                     __nv_bfloat16* __restrict__ Ch, __nv_bfloat16* __restrict__ Cl,
                     int M, int N, int K) {
    extern __shared__ char smem[];
    const uint32_t sb = smem_u32(smem);
    const int tid   = threadIdx.x;
    const int lane  = tid & 31;
    const int wid   = tid >> 5;
    const int warpM = wid & 1;            // 2 warps in M (64 rows each)
    const int warpN = wid >> 1;           // 2 warps in N (64 cols each)
    const int m0 = blockIdx.y * 128;
    const int n0 = blockIdx.x * 128;
    const int nch = K / KC;

    // 2048 x 16B per stage, 128 threads -> 16 ops each
    auto load_stage = [&](int kc0, int s) {
        const uint32_t stg = sb + s * STAGE_B;
#pragma unroll
        for (int t = 0; t < 16; t++) {
            const int id   = tid + t * 128;
            const int tile = id >> 9;             // 0:Ah 1:Al 2:Bh 3:Bl
            const int rem  = id & 511;
            const int row  = rem >> 2;
            const int q    = rem & 3;
            const __nv_bfloat16* src;
            if (tile == 0)      src = Ah  + (size_t)(m0 + row) * K + kc0 + q * 8;
            else if (tile == 1) src = Al  + (size_t)(m0 + row) * K + kc0 + q * 8;
            else if (tile == 2) src = BTh + (size_t)(n0 + row) * K + kc0 + q * 8;
            else                src = BTl + (size_t)(n0 + row) * K + kc0 + q * 8;
            CP_ASYNC16(stg + tile * TILE_B + row * TROW + q * 16, src);
        }
        CP_COMMIT();
    };

    float c[4][8][4];
#pragma unroll
    for (int i = 0; i < 4; i++)
#pragma unroll
        for (int j = 0; j < 8; j++)
#pragma unroll
            for (int r = 0; r < 4; r++) c[i][j][r] = 0.0f;

    const int arow = warpM * 64 + (lane & 15);
    const int acol = (lane >> 4) * 8;
    const int brow = warpN * 64 + (lane & 7) + ((lane >> 4) << 3);
    const int bck  = ((lane >> 3) & 1) * 8;

    load_stage(0, 0);
    load_stage(KC, 1);

    for (int ch = 0; ch < nch; ch++) {
        CP_WAIT(1);
        __syncthreads();

        const uint32_t stg = sb + (ch & 1) * STAGE_B;
        const uint32_t ahb = stg;
        const uint32_t alb = stg + TILE_B;
        const uint32_t bhb = stg + 2 * TILE_B;
        const uint32_t blb = stg + 3 * TILE_B;

#pragma unroll
        for (int k16 = 0; k16 < 2; k16++) {
            uint32_t fah[4][4], fal[4][4];
#pragma unroll
            for (int mt = 0; mt < 4; mt++) {
                uint32_t off = (uint32_t)(arow + mt * 16) * TROW + (k16 * 16 + acol) * 2;
                ldsm_x4(fah[mt][0], fah[mt][1], fah[mt][2], fah[mt][3], ahb + off);
                ldsm_x4(fal[mt][0], fal[mt][1], fal[mt][2], fal[mt][3], alb + off);
            }
#pragma unroll
            for (int np = 0; np < 4; np++) {
                uint32_t bh[4], bl[4];
                uint32_t off = (uint32_t)(brow + np * 16) * TROW + (k16 * 16 + bck) * 2;
                ldsm_x4(bh[0], bh[1], bh[2], bh[3], bhb + off);
                ldsm_x4(bl[0], bl[1], bl[2], bl[3], blb + off);
#pragma unroll
                for (int mt = 0; mt < 4; mt++)
#pragma unroll
                    for (int half = 0; half < 2; half++) {
                        float* acc = c[mt][np * 2 + half];
                        mma_bf16(acc, fah[mt], bh[half * 2], bh[half * 2 + 1]);
                        mma_bf16(acc, fah[mt], bl[half * 2], bl[half * 2 + 1]);
                        mma_bf16(acc, fal[mt], bh[half * 2], bh[half * 2 + 1]);
                    }
            }
        }
        __syncthreads();
        if (ch + 2 < nch) load_stage((ch + 2) * KC, ch & 1);
        else CP_COMMIT();   // placeholder group: keeps CP_WAIT(1) accounting exact
    }

    const int g   = lane >> 2;
    const int tig = lane & 3;
#pragma unroll
    for (int mt = 0; mt < 4; mt++) {
        const int row = m0 + warpM * 64 + mt * 16 + g;
#pragma unroll
        for (int nt = 0; nt < 8; nt++) {
            const int col = n0 + warpN * 64 + nt * 8 + tig * 2;
            if (MODE == 1) {
                float2 v0 = make_float2(c[mt][nt][0] + bias[col], c[mt][nt][1] + bias[col + 1]);
                float2 v1 = make_float2(c[mt][nt][2] + bias[col], c[mt][nt][3] + bias[col + 1]);
                *(float2*)(C + (size_t)row * N + col)       = v0;
                *(float2*)(C + (size_t)(row + 8) * N + col) = v1;
            } else {
                const float sc = (col < HID) ? QSF : 1.0f;
                uint32_t hp, lp;
                split_pack(c[mt][nt][0] * sc, c[mt][nt][1] * sc, hp, lp);
                *(uint32_t*)(Ch + (size_t)row * N + col) = hp;
                *(uint32_t*)(Cl + (size_t)row * N + col) = lp;
                split_pack(c[mt][nt][2] * sc, c[mt][nt][3] * sc, hp, lp);
                *(uint32_t*)(Ch + (size_t)(row + 8) * N + col) = hp;
                *(uint32_t*)(Cl + (size_t)(row + 8) * N + col) = lp;
            }
        }
    }
}

// ---------------------------------------------------------------------------
// mma.sync flash attention (bf16x3 both products). R4/R5-proven core.
// ---------------------------------------------------------------------------
#define ATROW 144
#define ATILE (64 * ATROW)           // 9216
#define ASTAGE (4 * ATILE)           // 36864: Kh | Kl | Vh | Vl
#define ATT_SMEM (2 * ASTAGE + 144)

__global__ __launch_bounds__(256, 1)
void mma_attn_kernel(const __nv_bfloat16* __restrict__ Qh, const __nv_bfloat16* __restrict__ Ql,
                     __nv_bfloat16* __restrict__ Oh, __nv_bfloat16* __restrict__ Ol) {
    extern __shared__ char sm[];
    const uint32_t sb = smem_u32(sm);
    int* list = (int*)(sm + 2 * ASTAGE);

    const int tid  = threadIdx.x;
    const int lane = tid & 31;
    const int w    = tid >> 5;
    const int b    = blockIdx.z;
    const int h    = blockIdx.y;
    const int q0   = blockIdx.x * 128;
    const int g    = lane >> 2;
    const int tq   = lane & 3;

    if (w == 0) {
        unsigned long long mb = g_mbits[b * 32 + lane];
        unsigned act = __ballot_sync(0xffffffffu, mb != 0ull);
        int pos = __popc(act & ((1u << lane) - 1));
        if (mb != 0ull) list[pos] = lane;
        if (lane == 0) list[32] = __popc(act);
    }
    __syncthreads();
    const int ncnt = list[32];

    uint32_t qfh[4][4], qfl[4][4];
    {
        const size_t qb = (size_t)(b * SEQ + q0 + w * 16) * QKV3 + h * HD;
#pragma unroll
        for (int kd = 0; kd < 4; kd++) {
            const int cc = kd * 16 + tq * 2;
            qfh[kd][0] = *(const uint32_t*)(Qh + qb + (size_t)g * QKV3 + cc);
            qfh[kd][1] = *(const uint32_t*)(Qh + qb + (size_t)(g + 8) * QKV3 + cc);
            qfh[kd][2] = *(const uint32_t*)(Qh + qb + (size_t)g * QKV3 + cc + 8);
            qfh[kd][3] = *(const uint32_t*)(Qh + qb + (size_t)(g + 8) * QKV3 + cc + 8);
            qfl[kd][0] = *(const uint32_t*)(Ql + qb + (size_t)g * QKV3 + cc);
            qfl[kd][1] = *(const uint32_t*)(Ql + qb + (size_t)(g + 8) * QKV3 + cc);
            qfl[kd][2] = *(const uint32_t*)(Ql + qb + (size_t)g * QKV3 + cc + 8);
            qfl[kd][3] = *(const uint32_t*)(Ql + qb + (size_t)(g + 8) * QKV3 + cc + 8);
        }
    }

    auto load_tile = [&](int kt, int stg) {
        const int tok0 = b * SEQ + kt * 64;
        const uint32_t base = sb + stg * ASTAGE;
#pragma unroll
        for (int t = 0; t < 8; t++) {
            const int id  = tid + t * 256;
            const int arr = id >> 9;
            const int rem = id & 511;
            const int r   = rem >> 3;
            const int q   = rem & 7;
            const size_t go = (size_t)(tok0 + r) * QKV3 + h * HD + q * 8;
            const __nv_bfloat16* src;
            if (arr == 0)      src = Qh + go + HID;
            else if (arr == 1) src = Ql + go + HID;
            else if (arr == 2) src = Qh + go + 2 * HID;
            else               src = Ql + go + 2 * HID;
            CP_ASYNC16(base + arr * ATILE + r * ATROW + q * 16, src);
        }
        CP_COMMIT();
    };

    float o[8][4];
#pragma unroll
    for (int j = 0; j < 8; j++)
#pragma unroll
        for (int r = 0; r < 4; r++) o[j][r] = 0.0f;
    float mi[2] = {-1e30f, -1e30f}, li[2] = {0.0f, 0.0f};

    if (ncnt > 0) load_tile(list[0], 0);

    for (int it = 0; it < ncnt; it++) {
        if (it + 1 < ncnt) { load_tile(list[it + 1], (it + 1) & 1); CP_WAIT(1); }
        else CP_WAIT(0);
        __syncthreads();
        const uint32_t st = sb + (it & 1) * ASTAGE;
        const int kt = list[it];

        float s[8][4];
#pragma unroll
        for (int j = 0; j < 8; j++)
#pragma unroll
            for (int r = 0; r < 4; r++) s[j][r] = 0.0f;

#pragma unroll
        for (int kd = 0; kd < 4; kd++) {
#pragma unroll
            for (int kg = 0; kg < 4; kg++) {
                uint32_t kh[4], kl[4];
                const uint32_t off = st + (uint32_t)(kg * 16 + (lane & 7) + ((lane >> 4) << 3)) * ATROW
                                        + (kd * 16 + ((lane >> 3) & 1) * 8) * 2;
                ldsm_x4(kh[0], kh[1], kh[2], kh[3], off);
                ldsm_x4(kl[0], kl[1], kl[2], kl[3], off + ATILE);
                mma_bf16(s[kg * 2],     qfh[kd], kh[0], kh[1]);
                mma_bf16(s[kg * 2],     qfh[kd], kl[0], kl[1]);
                mma_bf16(s[kg * 2],     qfl[kd], kh[0], kh[1]);
                mma_bf16(s[kg * 2 + 1], qfh[kd], kh[2], kh[3]);
                mma_bf16(s[kg * 2 + 1], qfh[kd], kl[2], kl[3]);
                mma_bf16(s[kg * 2 + 1], qfl[kd], kh[2], kh[3]);
            }
        }

        const unsigned long long mb = g_mbits[b * 32 + kt];
        if (mb != ~0ull) {
#pragma unroll
            for (int nf = 0; nf < 8; nf++) {
                const int c0 = nf * 8 + tq * 2;
                if (!((mb >> c0) & 1))       { s[nf][0] = -1e30f; s[nf][2] = -1e30f; }
                if (!((mb >> (c0 + 1)) & 1)) { s[nf][1] = -1e30f; s[nf][3] = -1e30f; }
            }
        }

#pragma unroll
        for (int r = 0; r < 2; r++) {
            float mx = -1e30f;
#pragma unroll
            for (int nf = 0; nf < 8; nf++)
                mx = fmaxf(mx, fmaxf(s[nf][2 * r], s[nf][2 * r + 1]));
            mx = fmaxf(mx, __shfl_xor_sync(0xffffffffu, mx, 1));
            mx = fmaxf(mx, __shfl_xor_sync(0xffffffffu, mx, 2));
            const float mnew = fmaxf(mi[r], mx);
            const float al = fexp2(mi[r] - mnew);
            mi[r] = mnew;
            li[r] *= al;
#pragma unroll
            for (int nf = 0; nf < 8; nf++) { o[nf][2 * r] *= al; o[nf][2 * r + 1] *= al; }
            float ls = 0.0f;
#pragma unroll
            for (int nf = 0; nf < 8; nf++) {
                const float p0 = fexp2(s[nf][2 * r] - mnew);
                const float p1 = fexp2(s[nf][2 * r + 1] - mnew);
                ls += p0 + p1;
                s[nf][2 * r] = p0;
                s[nf][2 * r + 1] = p1;
            }
            ls += __shfl_xor_sync(0xffffffffu, ls, 1);
            ls += __shfl_xor_sync(0xffffffffu, ls, 2);
            li[r] += ls;
        }

        uint32_t pah[4][4], pal[4][4];
#pragma unroll
        for (int ks = 0; ks < 4; ks++) {
            split_pack(s[2 * ks][0],     s[2 * ks][1],     pah[ks][0], pal[ks][0]);
            split_pack(s[2 * ks][2],     s[2 * ks][3],     pah[ks][1], pal[ks][1]);
            split_pack(s[2 * ks + 1][0], s[2 * ks + 1][1], pah[ks][2], pal[ks][2]);
            split_pack(s[2 * ks + 1][2], s[2 * ks + 1][3], pah[ks][3], pal[ks][3]);
        }

#pragma unroll
        for (int ks = 0; ks < 4; ks++) {
#pragma unroll
            for (int dg = 0; dg < 4; dg++) {
                uint32_t vh[4], vl[4];
                const uint32_t off = st + 2 * ATILE
                                   + (uint32_t)(ks * 16 + (lane & 15)) * ATROW
                                   + (dg * 16 + ((lane >> 4) << 3)) * 2;
                ldsm_x4t(vh[0], vh[1], vh[2], vh[3], off);
                ldsm_x4t(vl[0], vl[1], vl[2], vl[3], off + ATILE);
                mma_bf16(o[dg * 2],     pah[ks], vh[0], vh[1]);
                mma_bf16(o[dg * 2],     pah[ks], vl[0], vl[1]);
                mma_bf16(o[dg * 2],     pal[ks], vh[0], vh[1]);
                mma_bf16(o[dg * 2 + 1], pah[ks], vh[2], vh[3]);
                mma_bf16(o[dg * 2 + 1], pah[ks], vl[2], vl[3]);
                mma_bf16(o[dg * 2 + 1], pal[ks], vh[2], vh[3]);
            }
        }
        __syncthreads();
    }

#pragma unroll
    for (int r = 0; r < 2; r++) {
        const float inv = 1.0f / li[r];
        const size_t ob = (size_t)(b * SEQ + q0 + w * 16 + g + r * 8) * HID + h * HD;
#pragma unroll
        for (int nf = 0; nf < 8; nf++) {
            uint32_t hp, lp;
            split_pack(o[nf][2 * r] * inv, o[nf][2 * r + 1] * inv, hp, lp);
            *(uint32_t*)(Oh + ob + nf * 8 + tq * 2) = hp;
            *(uint32_t*)(Ol + ob + nf * 8 + tq * 2) = lp;
        }
    }
}

// ---------------------------------------------------------------------------
// Launch
// ---------------------------------------------------------------------------
extern "C" void kernel_launch(void* const* d_in, const int* in_sizes, int n_in,
                              void* d_out, int out_size) {
    const float* hidden = (const float*)d_in[0];
    const void*  maskp  = d_in[1];
    const float* Wqkv   = (const float*)d_in[2];
    const float* Wout   = (const float*)d_in[3];
    const float* bout   = (const float*)d_in[4];
    float*       out    = (float*)d_out;

    void *p_qh, *p_ql, *p_sh, *p_sl, *p_wh, *p_wl;
    cudaGetSymbolAddress(&p_qh, g_qh);
    cudaGetSymbolAddress(&p_ql, g_ql);
    cudaGetSymbolAddress(&p_sh, g_sh);
    cudaGetSymbolAddress(&p_sl, g_sl);
    cudaGetSymbolAddress(&p_wh, g_wh);
    cudaGetSymbolAddress(&p_wl, g_wl);

    cudaFuncSetAttribute(mma_gemm_kernel<0>,
                         cudaFuncAttributeMaxDynamicSharedMemorySize, TC_SMEM);
    cudaFuncSetAttribute(mma_gemm_kernel<1>,
                         cudaFuncAttributeMaxDynamicSharedMemorySize, TC_SMEM);
    cudaFuncSetAttribute(mma_attn_kernel,
                         cudaFuncAttributeMaxDynamicSharedMemorySize, ATT_SMEM);

    // 1. mask canonicalize + tile bitmasks
    mask_convert_kernel<<<1, 256>>>(maskp, BATCH * SEQ);

    // 2. split inputs to bf16 hi/lo
    splitA_kernel<<<592, 256>>>(hidden, (__nv_bfloat16*)p_sh, (__nv_bfloat16*)p_sl,
                                MROWS * HID / 4);
    splitBT_kernel<<<dim3(QKV3 / 32, HID / 32), 256>>>(
        Wqkv, (__nv_bfloat16*)p_wh, (__nv_bfloat16*)p_wl, HID, QKV3);
    splitBT_kernel<<<dim3(HID / 32, HID / 32), 256>>>(
        Wout, (__nv_bfloat16*)p_wh + (size_t)QKV3 * HID,
        (__nv_bfloat16*)p_wl + (size_t)QKV3 * HID, HID, HID);

    // 3. QKV projection -> bf16 hi/lo splits (Q pre-scaled by 0.125*log2e)
    mma_gemm_kernel<0><<<dim3(QKV3 / 128, MROWS / 128), 128, TC_SMEM>>>(
        (const __nv_bfloat16*)p_sh, (const __nv_bfloat16*)p_sl,
        (const __nv_bfloat16*)p_wh, (const __nv_bfloat16*)p_wl,
        nullptr, nullptr, (__nv_bfloat16*)p_qh, (__nv_bfloat16*)p_ql,
        MROWS, QKV3, HID);

    // 4. tensor-core flash attention -> bf16 hi/lo attention output
    mma_attn_kernel<<<dim3(SEQ / 128, NH, BATCH), 256, ATT_SMEM>>>(
        (const __nv_bfloat16*)p_qh, (const __nv_bfloat16*)p_ql,
        (__nv_bfloat16*)p_sh, (__nv_bfloat16*)p_sl);

    // 5. output projection (+bias)
    mma_gemm_kernel<1><<<dim3(HID / 128, MROWS / 128), 128, TC_SMEM>>>(
        (const __nv_bfloat16*)p_sh, (const __nv_bfloat16*)p_sl,
        (const __nv_bfloat16*)p_wh + (size_t)QKV3 * HID,
        (const __nv_bfloat16*)p_wl + (size_t)QKV3 * HID,
        bout, out, nullptr, nullptr, MROWS, HID, HID);
}